// round 1
// baseline (speedup 1.0000x reference)
#include <cuda_runtime.h>

// Shapes
#define B_LEN 32
#define T_IN  128
#define T_LEN 129      // after conv1 (pad 2, k 4)
#define M_LEN 40
#define C_LEN 64
#define NTOT  (B_LEN*T_LEN*M_LEN*C_LEN)   // 10,567,680 floats

// Scratch (device globals; no allocation allowed). float4 for 16B alignment.
__device__ float4 g_bufA[NTOT/4];
__device__ float4 g_bufB[NTOT/4];
__device__ float4 g_wt2[(64*12*64)/4];   // [co][tap][ci]
__device__ float4 g_wt3[(64*12*64)/4];
__device__ float4 g_wft[(12*40*64)/4];   // [o][m][c]
__device__ float  g_cnt[B_LEN*M_LEN*C_LEN];

__device__ __forceinline__ float lif_tau_div(float num) {
    const float TAUF = 10.0f / 7.0f;
    return __fdiv_rn(num, TAUF);
}

// ---------------- weight transposes ----------------
// wt[co][tap][ci] = w[co][ci][kh][kw], tap = kh*3+kw
__global__ void k_transpose_w(const float* __restrict__ w, int which) {
    int i = blockIdx.x * 256 + threadIdx.x;
    if (i >= 64 * 12 * 64) return;
    int ci  = i & 63;
    int tap = (i >> 6) % 12;
    int co  = i / 768;
    float* wt = which ? (float*)g_wt3 : (float*)g_wt2;
    wt[i] = w[co * 768 + ci * 12 + tap];
}

// wft[o][m][c] = wf[o][c*40+m]
__global__ void k_transpose_wf(const float* __restrict__ wf) {
    int i = blockIdx.x * 256 + threadIdx.x;
    if (i >= 12 * 40 * 64) return;
    int c = i & 63;
    int m = (i >> 6) % 40;
    int o = i / 2560;
    ((float*)g_wft)[i] = wf[o * 2560 + c * 40 + m];
}

// ---------------- conv1 (C_in=1) fused with LIF1 ----------------
// grid (32, 5), block (64, 8). Output spikes -> g_bufA, layout [b][t][m][c].
__global__ void k_conv1_lif(const float* __restrict__ x, const float* __restrict__ w1) {
    __shared__ float xs[T_IN][10];   // cols m0-1 .. m0+8
    int b  = blockIdx.x;
    int m0 = blockIdx.y * 8;
    int co = threadIdx.x;
    int mj = threadIdx.y;
    int tid = co + 64 * mj;

    for (int i = tid; i < T_IN * 10; i += 512) {
        int tt  = i / 10;
        int col = i % 10;
        int mi  = m0 - 1 + col;
        xs[tt][col] = ((unsigned)mi < (unsigned)M_LEN) ? x[(b * T_IN + tt) * M_LEN + mi] : 0.0f;
    }
    float w[12];
#pragma unroll
    for (int k = 0; k < 12; ++k) w[k] = w1[co * 12 + k];
    __syncthreads();

    int m = m0 + mj;
    float* out = (float*)g_bufA;
    float v = 0.0f;
    for (int t = 0; t < T_LEN; ++t) {
        float acc = 0.0f;
#pragma unroll
        for (int kh = 0; kh < 4; ++kh) {
            int ti = t - 2 + kh;
            if ((unsigned)ti < (unsigned)T_IN) {
#pragma unroll
                for (int kw = 0; kw < 3; ++kw)
                    acc = fmaf(w[kh * 3 + kw], xs[ti][mj + kw], acc);
            }
        }
        v = v + lif_tau_div(acc - v);
        float s = (v >= 1.0f) ? 1.0f : 0.0f;
        v = (v >= 1.0f) ? 0.0f : v;
        out[((b * T_LEN + t) * M_LEN + m) * C_LEN + co] = s;
    }
}

// ---------------- generic dilated conv (64->64, k 4x3) ----------------
// grid (129, 32, 2), block 128. Each thread: 2 co x 5 m outputs.
// which=0: A -> B (conv2 params). which=1: B -> A (conv3 params).
template<int PADT, int DILT, int PADM, int DILM, int WHICH>
__global__ void __launch_bounds__(128) k_conv(void) {
    const int MPT = 20 + 2 * PADM;           // padded m-extent for a 20-wide m tile
    __shared__ float4 sm[4 * MPT * 16];      // [kh][mp][ci4]

    const float4* S  = WHICH ? (const float4*)g_bufB : (const float4*)g_bufA;
    float*        O  = WHICH ? (float*)g_bufA        : (float*)g_bufB;
    const float4* W4 = WHICH ? (const float4*)g_wt3  : (const float4*)g_wt2;

    int t   = blockIdx.x;
    int b   = blockIdx.y;
    int mt  = blockIdx.z;                    // m tile: 0 or 1 (20 each)
    int tid = threadIdx.x;

    for (int i = tid; i < 4 * MPT * 16; i += 128) {
        int kh = i / (MPT * 16);
        int r  = i % (MPT * 16);
        int mp = r >> 4;
        int q  = r & 15;
        int ti = t - PADT + DILT * kh;
        int mi = mt * 20 + mp - PADM;
        float4 v = make_float4(0.f, 0.f, 0.f, 0.f);
        if ((unsigned)ti < (unsigned)T_LEN && (unsigned)mi < (unsigned)M_LEN)
            v = S[((b * T_LEN + ti) * M_LEN + mi) * 16 + q];
        sm[i] = v;
    }
    __syncthreads();

    int co0 = (tid & 31) * 2;
    int mg  = tid >> 5;                      // 0..3, 5 m each
    float acc0[5], acc1[5];
#pragma unroll
    for (int j = 0; j < 5; ++j) { acc0[j] = 0.f; acc1[j] = 0.f; }

#pragma unroll
    for (int kh = 0; kh < 4; ++kh) {
#pragma unroll
        for (int kw = 0; kw < 3; ++kw) {
            int tap = kh * 3 + kw;
            const float4* wa = W4 + (co0 * 12 + tap) * 16;
            const float4* wb = W4 + ((co0 + 1) * 12 + tap) * 16;
            const float4* sr = sm + (kh * MPT + mg * 5 + DILM * kw) * 16;
#pragma unroll 4
            for (int q = 0; q < 16; ++q) {
                float4 A  = wa[q];
                float4 Bv = wb[q];
#pragma unroll
                for (int j = 0; j < 5; ++j) {
                    float4 s = sr[j * 16 + q];
                    acc0[j] = fmaf(A.x,  s.x, acc0[j]);
                    acc0[j] = fmaf(A.y,  s.y, acc0[j]);
                    acc0[j] = fmaf(A.z,  s.z, acc0[j]);
                    acc0[j] = fmaf(A.w,  s.w, acc0[j]);
                    acc1[j] = fmaf(Bv.x, s.x, acc1[j]);
                    acc1[j] = fmaf(Bv.y, s.y, acc1[j]);
                    acc1[j] = fmaf(Bv.z, s.z, acc1[j]);
                    acc1[j] = fmaf(Bv.w, s.w, acc1[j]);
                }
            }
        }
    }

    float2* o2 = (float2*)O;
#pragma unroll
    for (int j = 0; j < 5; ++j) {
        int m = mt * 20 + mg * 5 + j;
        o2[(((b * T_LEN + t) * M_LEN + m) * C_LEN + co0) >> 1] = make_float2(acc0[j], acc1[j]);
    }
}

// ---------------- in-place LIF over T ----------------
__global__ void k_lif(int which) {
    int i = blockIdx.x * 256 + threadIdx.x;
    if (i >= B_LEN * M_LEN * C_LEN) return;
    float* buf = which ? (float*)g_bufA : (float*)g_bufB;
    int b  = i / (M_LEN * C_LEN);
    int mc = i % (M_LEN * C_LEN);
    float* p = buf + (size_t)b * T_LEN * M_LEN * C_LEN + mc;
    float v = 0.0f;
    for (int t = 0; t < T_LEN; ++t) {
        float xv = p[(size_t)t * M_LEN * C_LEN];
        v = v + lif_tau_div(xv - v);
        float s = (v >= 1.0f) ? 1.0f : 0.0f;
        v = (v >= 1.0f) ? 0.0f : v;
        p[(size_t)t * M_LEN * C_LEN] = s;
    }
}

// ---------------- time-sum of spikes (exact integers) ----------------
__global__ void k_cnt(void) {
    int i = blockIdx.x * 256 + threadIdx.x;
    if (i >= B_LEN * M_LEN * C_LEN) return;
    const float* S = (const float*)g_bufA;   // s3 lives in A
    int b  = i / (M_LEN * C_LEN);
    int mc = i % (M_LEN * C_LEN);
    const float* p = S + (size_t)b * T_LEN * M_LEN * C_LEN + mc;
    float s = 0.0f;
    for (int t = 0; t < T_LEN; ++t) s += p[(size_t)t * M_LEN * C_LEN];
    g_cnt[i] = s;
}

// ---------------- FC + mean: y[b,o] = bf[o] + (cnt[b]·wft[o]) / 129 ----------------
__global__ void k_fc(const float* __restrict__ bf, float* __restrict__ out) {
    int o = blockIdx.x;
    int b = blockIdx.y;
    int tid = threadIdx.x;   // 128
    const float* wft = (const float*)g_wft;
    float p = 0.0f;
    for (int i = tid; i < 2560; i += 128)
        p = fmaf(g_cnt[b * 2560 + i], wft[o * 2560 + i], p);
#pragma unroll
    for (int off = 16; off; off >>= 1) p += __shfl_down_sync(0xffffffffu, p, off);
    __shared__ float ws[4];
    if ((tid & 31) == 0) ws[tid >> 5] = p;
    __syncthreads();
    if (tid == 0) {
        float tt = ws[0] + ws[1] + ws[2] + ws[3];
        out[b * 12 + o] = bf[o] + tt / 129.0f;
    }
}

extern "C" void kernel_launch(void* const* d_in, const int* in_sizes, int n_in,
                              void* d_out, int out_size) {
    const float* x  = (const float*)d_in[0];
    const float* w1 = (const float*)d_in[1];
    const float* w2 = (const float*)d_in[2];
    const float* w3 = (const float*)d_in[3];
    const float* wf = (const float*)d_in[4];
    const float* bf = (const float*)d_in[5];
    float* out = (float*)d_out;

    // weight layouts
    k_transpose_w<<<192, 256>>>(w2, 0);
    k_transpose_w<<<192, 256>>>(w3, 1);
    k_transpose_wf<<<120, 256>>>(wf);

    // conv1 + LIF1 -> A
    k_conv1_lif<<<dim3(32, 5), dim3(64, 8)>>>(x, w1);

    // conv2: A -> B  (pad (6,3), dil (4,3)), then LIF2 in-place on B
    k_conv<6, 4, 3, 3, 0><<<dim3(T_LEN, B_LEN, 2), 128>>>();
    k_lif<<<320, 256>>>(0);

    // conv3: B -> A  (pad (24,9), dil (16,9)), then LIF3 in-place on A
    k_conv<24, 16, 9, 9, 1><<<dim3(T_LEN, B_LEN, 2), 128>>>();
    k_lif<<<320, 256>>>(1);

    // FC head
    k_cnt<<<320, 256>>>();
    k_fc<<<dim3(12, 32), 128>>>(bf, out);
}

// round 2
// speedup vs baseline: 3.7625x; 3.7625x over previous
#include <cuda_runtime.h>

#define B_LEN 32
#define T_IN  128
#define T_LEN 129
#define M_LEN 40
#define C_LEN 64
#define NPIX  (B_LEN*T_LEN*M_LEN)

// Spike bitmasks: [pix][2] uint32 halves; co = half*32 + lane
__device__ unsigned int g_mask1[NPIX * 2];
__device__ unsigned int g_mask2[NPIX * 2];
// Weights transposed: float index = tap*4096 + ci*64 + lane*2 + half  (co = half*32+lane)
__device__ float4 g_wt2[(12 * 64 * 64) / 4];
__device__ float4 g_wt3[(12 * 64 * 64) / 4];
__device__ float4 g_wft[(12 * 40 * 64) / 4];   // [o][m][c]
__device__ float  g_cnt[B_LEN * M_LEN * C_LEN]; // [b][m][c]

__device__ __forceinline__ float lif_tau_div(float num) {
    const float TAUF = 10.0f / 7.0f;
    return __fdiv_rn(num, TAUF);
}

// ---------------- weight transposes ----------------
// dst[tap*4096 + ci*64 + (co&31)*2 + (co>>5)] = w[co*768 + ci*12 + tap]
__global__ void k_transpose_w(const float* __restrict__ w, int which) {
    int i = blockIdx.x * 256 + threadIdx.x;
    if (i >= 64 * 12 * 64) return;
    int ci  = i & 63;
    int tap = (i >> 6) % 12;
    int co  = i / 768;
    float* wt = which ? (float*)g_wt3 : (float*)g_wt2;
    wt[tap * 4096 + ci * 64 + (co & 31) * 2 + (co >> 5)] = w[co * 768 + ci * 12 + tap];
}

// wft[o][m][c] = wf[o][c*40+m]
__global__ void k_transpose_wf(const float* __restrict__ wf) {
    int i = blockIdx.x * 256 + threadIdx.x;
    if (i >= 12 * 40 * 64) return;
    int c = i & 63;
    int m = (i >> 6) % 40;
    int o = i / 2560;
    ((float*)g_wft)[i] = wf[o * 2560 + c * 40 + m];
}

// ---------------- conv1 (C_in=1) fused with LIF1 -> bitmasks ----------------
// grid (32, 5), block (64, 8). Warp = 32 consecutive co for one m.
__global__ void k_conv1_lif(const float* __restrict__ x, const float* __restrict__ w1) {
    __shared__ float xs[T_IN][10];
    int b  = blockIdx.x;
    int m0 = blockIdx.y * 8;
    int co = threadIdx.x;
    int mj = threadIdx.y;
    int tid = co + 64 * mj;

    for (int i = tid; i < T_IN * 10; i += 512) {
        int tt  = i / 10;
        int col = i % 10;
        int mi  = m0 - 1 + col;
        xs[tt][col] = ((unsigned)mi < (unsigned)M_LEN) ? x[(b * T_IN + tt) * M_LEN + mi] : 0.0f;
    }
    float w[12];
#pragma unroll
    for (int k = 0; k < 12; ++k) w[k] = w1[co * 12 + k];
    __syncthreads();

    int m = m0 + mj;
    float v = 0.0f;
    for (int t = 0; t < T_LEN; ++t) {
        float acc = 0.0f;
#pragma unroll
        for (int kh = 0; kh < 4; ++kh) {
            int ti = t - 2 + kh;
            if ((unsigned)ti < (unsigned)T_IN) {
#pragma unroll
                for (int kw = 0; kw < 3; ++kw)
                    acc = fmaf(w[kh * 3 + kw], xs[ti][mj + kw], acc);
            }
        }
        v = v + lif_tau_div(acc - v);
        bool sp = (v >= 1.0f);
        if (sp) v = 0.0f;
        unsigned bal = __ballot_sync(0xffffffffu, sp);
        if ((co & 31) == 0)
            g_mask1[((b * T_LEN + t) * M_LEN + m) * 2 + (co >> 5)] = bal;
    }
}

// ---------------- sparse conv (masked weight-sum) + LIF fused ----------------
// 1 warp per (b,m) chain; lane handles co=lane and co=lane+32.
// WHICH=0: mask1 -> conv2 -> LIF -> mask2.  WHICH=1: mask2 -> conv3 -> LIF -> spike counts.
template<int PADT, int DILT, int PADM, int DILM, int WHICH>
__global__ void __launch_bounds__(320, 1) k_sconv(void) {
    extern __shared__ float2 ws[];   // [tap][ci][lane] float2 = 12*64*32
    const float4* Wg = WHICH ? (const float4*)g_wt3 : (const float4*)g_wt2;
    float4* ws4 = (float4*)ws;
    for (int i = threadIdx.x; i < 12288; i += 320) ws4[i] = Wg[i];
    __syncthreads();

    int g    = threadIdx.x >> 5;
    int lane = threadIdx.x & 31;
    int id   = blockIdx.x * 10 + g;
    int b    = id / 40;
    int m    = id % 40;
    const unsigned long long* msk_in =
        (const unsigned long long*)(WHICH ? g_mask2 : g_mask1);

    float v0 = 0.f, v1 = 0.f, c0 = 0.f, c1 = 0.f;
    for (int t = 0; t < T_LEN; ++t) {
        float a0 = 0.f, a1 = 0.f;
#pragma unroll
        for (int kh = 0; kh < 4; ++kh) {
            int ti = t - PADT + DILT * kh;
            if ((unsigned)ti >= (unsigned)T_LEN) continue;
#pragma unroll
            for (int kw = 0; kw < 3; ++kw) {
                int mi = m - PADM + DILM * kw;
                if ((unsigned)mi >= (unsigned)M_LEN) continue;
                unsigned long long mk = msk_in[(b * T_LEN + ti) * M_LEN + mi];
                const float2* wt = ws + (kh * 3 + kw) * 2048 + lane;
                while (mk) {
                    int ci = __ffsll((long long)mk) - 1;   // ascending ci order (exactness)
                    mk &= (mk - 1);
                    float2 w = wt[ci << 5];
                    a0 += w.x;
                    a1 += w.y;
                }
            }
        }
        v0 = v0 + lif_tau_div(a0 - v0);
        v1 = v1 + lif_tau_div(a1 - v1);
        bool s0 = (v0 >= 1.0f);
        bool s1 = (v1 >= 1.0f);
        if (s0) v0 = 0.0f;
        if (s1) v1 = 0.0f;
        if (WHICH == 0) {
            unsigned bl = __ballot_sync(0xffffffffu, s0);
            unsigned bh = __ballot_sync(0xffffffffu, s1);
            if (lane == 0) {
                int pix = (b * T_LEN + t) * M_LEN + m;
                g_mask2[pix * 2]     = bl;
                g_mask2[pix * 2 + 1] = bh;
            }
        } else {
            c0 += s0 ? 1.0f : 0.0f;
            c1 += s1 ? 1.0f : 0.0f;
        }
    }
    if (WHICH == 1) {
        g_cnt[b * 2560 + m * 64 + lane]      = c0;
        g_cnt[b * 2560 + m * 64 + lane + 32] = c1;
    }
}

// ---------------- FC + mean: y[b,o] = bf[o] + (cnt[b]·wft[o]) / 129 ----------------
__global__ void k_fc(const float* __restrict__ bf, float* __restrict__ out) {
    int o = blockIdx.x;
    int b = blockIdx.y;
    int tid = threadIdx.x;   // 128
    const float* wft = (const float*)g_wft;
    float p = 0.0f;
    for (int i = tid; i < 2560; i += 128)
        p = fmaf(g_cnt[b * 2560 + i], wft[o * 2560 + i], p);
#pragma unroll
    for (int off = 16; off; off >>= 1) p += __shfl_down_sync(0xffffffffu, p, off);
    __shared__ float wsum[4];
    if ((tid & 31) == 0) wsum[tid >> 5] = p;
    __syncthreads();
    if (tid == 0) {
        float tt = wsum[0] + wsum[1] + wsum[2] + wsum[3];
        out[b * 12 + o] = bf[o] + tt / 129.0f;
    }
}

#define SCONV_SMEM (12 * 64 * 64 * 4)   // 196608 bytes

extern "C" void kernel_launch(void* const* d_in, const int* in_sizes, int n_in,
                              void* d_out, int out_size) {
    const float* x  = (const float*)d_in[0];
    const float* w1 = (const float*)d_in[1];
    const float* w2 = (const float*)d_in[2];
    const float* w3 = (const float*)d_in[3];
    const float* wf = (const float*)d_in[4];
    const float* bf = (const float*)d_in[5];
    float* out = (float*)d_out;

    cudaFuncSetAttribute(k_sconv<6, 4, 3, 3, 0>,
                         cudaFuncAttributeMaxDynamicSharedMemorySize, SCONV_SMEM);
    cudaFuncSetAttribute(k_sconv<24, 16, 9, 9, 1>,
                         cudaFuncAttributeMaxDynamicSharedMemorySize, SCONV_SMEM);

    // weight layouts
    k_transpose_w<<<192, 256>>>(w2, 0);
    k_transpose_w<<<192, 256>>>(w3, 1);
    k_transpose_wf<<<120, 256>>>(wf);

    // conv1 + LIF1 -> mask1
    k_conv1_lif<<<dim3(32, 5), dim3(64, 8)>>>(x, w1);

    // conv2 + LIF2 -> mask2 (sparse masked weight-sum)
    k_sconv<6, 4, 3, 3, 0><<<128, 320, SCONV_SMEM>>>();

    // conv3 + LIF3 -> spike counts (sparse)
    k_sconv<24, 16, 9, 9, 1><<<128, 320, SCONV_SMEM>>>();

    // FC head
    k_fc<<<dim3(12, 32), 128>>>(bf, out);
}

// round 3
// speedup vs baseline: 5.8196x; 1.5467x over previous
#include <cuda_runtime.h>

#define B_LEN 32
#define T_IN  128
#define T_LEN 129
#define M_LEN 40
#define C_LEN 64
#define NPIX  (B_LEN*T_LEN*M_LEN)            // 165,120
#define NTOT  (NPIX*C_LEN)                   // 10,567,680

// Scratch (device globals; allocation forbidden)
__device__ float  g_actA[NTOT];              // pre-activations [pix][64]
__device__ float  g_actB[NTOT];
__device__ unsigned int g_mask1[NPIX * 2];   // spike bitmasks, co = half*32+lane
__device__ unsigned int g_mask2[NPIX * 2];
// Weights transposed: float idx = tap*4096 + ci*64 + lane*2 + half  (co = half*32+lane)
__device__ float4 g_wt2[(12 * 64 * 64) / 4];
__device__ float4 g_wt3[(12 * 64 * 64) / 4];
__device__ float4 g_wft[(12 * 40 * 64) / 4]; // [o][m][c]
__device__ float  g_cnt[B_LEN * M_LEN * C_LEN]; // [b][m][c]

__device__ __forceinline__ float lif_tau_div(float num) {
    const float TAUF = 10.0f / 7.0f;
    return __fdiv_rn(num, TAUF);
}

// ---------------- weight transposes ----------------
__global__ void k_transpose_w(const float* __restrict__ w, int which) {
    int i = blockIdx.x * 256 + threadIdx.x;
    if (i >= 64 * 12 * 64) return;
    int ci  = i & 63;
    int tap = (i >> 6) % 12;
    int co  = i / 768;
    float* wt = which ? (float*)g_wt3 : (float*)g_wt2;
    wt[tap * 4096 + ci * 64 + (co & 31) * 2 + (co >> 5)] = w[co * 768 + ci * 12 + tap];
}

__global__ void k_transpose_wf(const float* __restrict__ wf) {
    int i = blockIdx.x * 256 + threadIdx.x;
    if (i >= 12 * 40 * 64) return;
    int c = i & 63;
    int m = (i >> 6) % 40;
    int o = i / 2560;
    ((float*)g_wft)[i] = wf[o * 2560 + c * 40 + m];
}

// ---------------- conv1: dense, fully parallel over pixels ----------------
// grid (T_LEN, B_LEN), block (64, 8). Each thread: co, 5 m values.
__global__ void k_conv1(const float* __restrict__ x, const float* __restrict__ w1) {
    __shared__ float xs[4][42];   // rows t-2..t+1, cols m=-1..40
    int t  = blockIdx.x;
    int b  = blockIdx.y;
    int co = threadIdx.x;
    int mj = threadIdx.y;
    int tid = co + 64 * mj;

    for (int i = tid; i < 4 * 42; i += 512) {
        int r  = i / 42;
        int mi = i % 42 - 1;
        int ti = t - 2 + r;
        xs[r][i % 42] = ((unsigned)ti < (unsigned)T_IN && (unsigned)mi < (unsigned)M_LEN)
                        ? x[(b * T_IN + ti) * M_LEN + mi] : 0.0f;
    }
    float w[12];
#pragma unroll
    for (int k = 0; k < 12; ++k) w[k] = w1[co * 12 + k];
    __syncthreads();

    float* out = g_actA + ((size_t)(b * T_LEN + t) * M_LEN) * 64;
#pragma unroll
    for (int mg = 0; mg < 5; ++mg) {
        int m = mg * 8 + mj;
        float acc = 0.0f;
#pragma unroll
        for (int kh = 0; kh < 4; ++kh)
#pragma unroll
            for (int kw = 0; kw < 3; ++kw)
                acc = fmaf(w[kh * 3 + kw], xs[kh][m + kw], acc);
        out[m * 64 + co] = acc;
    }
}

// ---------------- LIF scan over T (the only sequential part) ----------------
// warp per (b,m) chain; lane handles co=lane and co=lane+32.
// MODE 0: emit bitmasks. MODE 1: emit spike counts.
template<int MODE>
__global__ void k_lif_scan(const float* __restrict__ acts, unsigned* __restrict__ mask_out) {
    int wid  = (blockIdx.x * blockDim.x + threadIdx.x) >> 5;
    int lane = threadIdx.x & 31;
    if (wid >= B_LEN * M_LEN) return;
    int b = wid / M_LEN;
    int m = wid % M_LEN;
    const float* p = acts + ((size_t)b * T_LEN * M_LEN + m) * 64;

    float v0 = 0.f, v1 = 0.f, c0 = 0.f, c1 = 0.f;
    for (int t = 0; t < T_LEN; ++t) {
        const float* q = p + (size_t)t * M_LEN * 64;
        float a0 = q[lane];
        float a1 = q[lane + 32];
        v0 = v0 + lif_tau_div(a0 - v0);
        v1 = v1 + lif_tau_div(a1 - v1);
        bool s0 = (v0 >= 1.0f);
        bool s1 = (v1 >= 1.0f);
        if (s0) v0 = 0.0f;
        if (s1) v1 = 0.0f;
        if (MODE == 0) {
            unsigned bl = __ballot_sync(0xffffffffu, s0);
            unsigned bh = __ballot_sync(0xffffffffu, s1);
            if (lane == 0) {
                int pix = (b * T_LEN + t) * M_LEN + m;
                mask_out[pix * 2]     = bl;
                mask_out[pix * 2 + 1] = bh;
            }
        } else {
            c0 += s0 ? 1.0f : 0.0f;
            c1 += s1 ? 1.0f : 0.0f;
        }
    }
    if (MODE == 1) {
        g_cnt[b * 2560 + m * 64 + lane]      = c0;
        g_cnt[b * 2560 + m * 64 + lane + 32] = c1;
    }
}

// ---------------- sparse conv: warp per pixel, masked weight-sum ----------------
// WHICH=0: weights g_wt2, WHICH=1: g_wt3. Output: dense pre-activations.
template<int PADT, int DILT, int PADM, int DILM, int WHICH>
__global__ void __launch_bounds__(1024, 1) k_sconv(const unsigned int* __restrict__ msk32,
                                                   float* __restrict__ acts_out) {
    extern __shared__ float2 ws[];   // [tap][ci][lane] float2
    const float4* Wg = WHICH ? (const float4*)g_wt3 : (const float4*)g_wt2;
    float4* ws4 = (float4*)ws;
    for (int i = threadIdx.x; i < 12288; i += 1024) ws4[i] = Wg[i];
    __syncthreads();

    const unsigned long long* msk_in = (const unsigned long long*)msk32;
    int lane = threadIdx.x & 31;
    int wid  = (blockIdx.x * 1024 + threadIdx.x) >> 5;
    int nw   = gridDim.x * 32;

    for (int pix = wid; pix < NPIX; pix += nw) {
        int b = pix / (T_LEN * M_LEN);
        int r = pix % (T_LEN * M_LEN);
        int t = r / M_LEN;
        int m = r % M_LEN;
        float a0 = 0.f, a1 = 0.f;
#pragma unroll
        for (int kh = 0; kh < 4; ++kh) {
            int ti = t - PADT + DILT * kh;
            if ((unsigned)ti >= (unsigned)T_LEN) continue;
#pragma unroll
            for (int kw = 0; kw < 3; ++kw) {
                int mi = m - PADM + DILM * kw;
                if ((unsigned)mi >= (unsigned)M_LEN) continue;
                unsigned long long mk = msk_in[(b * T_LEN + ti) * M_LEN + mi];
                const float2* wt = ws + (kh * 3 + kw) * 2048 + lane;
                while (mk) {
                    int ci = __ffsll((long long)mk) - 1;  // ascending ci (order preserved)
                    mk &= (mk - 1);
                    float2 w = wt[ci << 5];
                    a0 += w.x;
                    a1 += w.y;
                }
            }
        }
        acts_out[(size_t)pix * 64 + lane]      = a0;
        acts_out[(size_t)pix * 64 + lane + 32] = a1;
    }
}

// ---------------- FC + mean ----------------
__global__ void k_fc(const float* __restrict__ bf, float* __restrict__ out) {
    int o = blockIdx.x;
    int b = blockIdx.y;
    int tid = threadIdx.x;   // 128
    const float* wft = (const float*)g_wft;
    float p = 0.0f;
    for (int i = tid; i < 2560; i += 128)
        p = fmaf(g_cnt[b * 2560 + i], wft[o * 2560 + i], p);
#pragma unroll
    for (int off = 16; off; off >>= 1) p += __shfl_down_sync(0xffffffffu, p, off);
    __shared__ float wsum[4];
    if ((tid & 31) == 0) wsum[tid >> 5] = p;
    __syncthreads();
    if (tid == 0) {
        float tt = wsum[0] + wsum[1] + wsum[2] + wsum[3];
        out[b * 12 + o] = bf[o] + tt / 129.0f;
    }
}

#define SCONV_SMEM (12 * 64 * 64 * 4)   // 196608 bytes

extern "C" void kernel_launch(void* const* d_in, const int* in_sizes, int n_in,
                              void* d_out, int out_size) {
    const float* x  = (const float*)d_in[0];
    const float* w1 = (const float*)d_in[1];
    const float* w2 = (const float*)d_in[2];
    const float* w3 = (const float*)d_in[3];
    const float* wf = (const float*)d_in[4];
    const float* bf = (const float*)d_in[5];
    float* out = (float*)d_out;

    static int smem_set = 0;
    // cudaFuncSetAttribute is host-side, not a graph node; idempotent and cheap.
    cudaFuncSetAttribute(k_sconv<6, 4, 3, 3, 0>,
                         cudaFuncAttributeMaxDynamicSharedMemorySize, SCONV_SMEM);
    cudaFuncSetAttribute(k_sconv<24, 16, 9, 9, 1>,
                         cudaFuncAttributeMaxDynamicSharedMemorySize, SCONV_SMEM);
    (void)smem_set;

    unsigned int* m1 = nullptr; cudaGetSymbolAddress((void**)&m1, g_mask1);
    unsigned int* m2 = nullptr; cudaGetSymbolAddress((void**)&m2, g_mask2);
    float* aA = nullptr; cudaGetSymbolAddress((void**)&aA, g_actA);
    float* aB = nullptr; cudaGetSymbolAddress((void**)&aB, g_actB);

    // weight layouts
    k_transpose_w<<<192, 256>>>(w2, 0);
    k_transpose_w<<<192, 256>>>(w3, 1);
    k_transpose_wf<<<120, 256>>>(wf);

    // layer 1: dense conv -> LIF -> mask1
    k_conv1<<<dim3(T_LEN, B_LEN), dim3(64, 8)>>>(x, w1);
    k_lif_scan<0><<<80, 1024>>>(aA, m1);

    // layer 2: sparse conv -> LIF -> mask2
    k_sconv<6, 4, 3, 3, 0><<<148, 1024, SCONV_SMEM>>>(m1, aB);
    k_lif_scan<0><<<80, 1024>>>(aB, m2);

    // layer 3: sparse conv -> LIF -> counts
    k_sconv<24, 16, 9, 9, 1><<<148, 1024, SCONV_SMEM>>>(m2, aA);
    k_lif_scan<1><<<80, 1024>>>(aA, nullptr);

    // FC head
    k_fc<<<dim3(12, 32), 128>>>(bf, out);
}

// round 4
// speedup vs baseline: 7.2555x; 1.2467x over previous
#include <cuda_runtime.h>

#define B_LEN 32
#define T_IN  128
#define T_LEN 129
#define M_LEN 40
#define C_LEN 64
#define NPIX  (B_LEN*T_LEN*M_LEN)            // 165,120
#define NTOT  (NPIX*C_LEN)                   // 10,567,680

__device__ float  g_actA[NTOT];              // pre-activations [pix][64]
__device__ unsigned int g_mask1[NPIX * 2];   // co = half*32 + lane
__device__ unsigned int g_mask2[NPIX * 2];
// Weights transposed: float idx = tap*4096 + ci*64 + lane*2 + half
__device__ float4 g_wt2[(12 * 64 * 64) / 4];
__device__ float4 g_wt3[(12 * 64 * 64) / 4];
__device__ float4 g_wft[(12 * 40 * 64) / 4]; // [o][m][c]
__device__ float  g_cnt[B_LEN * M_LEN * C_LEN]; // [b][m][c]

__device__ __forceinline__ float lif_tau_div(float num) {
    const float TAUF = 10.0f / 7.0f;
    return __fdiv_rn(num, TAUF);
}

// ---------------- all weight transposes in one launch ----------------
__global__ void k_transpose(const float* __restrict__ w2, const float* __restrict__ w3,
                            const float* __restrict__ wf) {
    int i = blockIdx.x * 256 + threadIdx.x;
    if (i < 2 * 49152) {
        int which = i >= 49152;
        int j = i - which * 49152;
        int ci  = j & 63;
        int tap = (j >> 6) % 12;
        int co  = j / 768;
        const float* w = which ? w3 : w2;
        float* wt = which ? (float*)g_wt3 : (float*)g_wt2;
        wt[tap * 4096 + ci * 64 + (co & 31) * 2 + (co >> 5)] = w[co * 768 + ci * 12 + tap];
    } else if (i < 2 * 49152 + 30720) {
        int j = i - 2 * 49152;
        int c = j & 63;
        int m = (j >> 6) % 40;
        int o = j / 2560;
        ((float*)g_wft)[j] = wf[o * 2560 + c * 40 + m];
    }
}

// ---------------- conv1 + LIF1 fused: warp per (b,m,half) chain ----------------
// 2560 warps. Rolling 4x3 register window over x; 3 uniform loads per t.
__global__ void __launch_bounds__(1024) k_conv1_lif(const float* __restrict__ x,
                                                    const float* __restrict__ w1) {
    int w    = (blockIdx.x * 1024 + threadIdx.x) >> 5;
    int lane = threadIdx.x & 31;
    int b    = w / 80;
    int r    = w % 80;
    int m    = r >> 1;
    int half = r & 1;
    int co   = half * 32 + lane;

    float wr[12];
#pragma unroll
    for (int k = 0; k < 12; ++k) wr[k] = w1[co * 12 + k];

    const float* xb = x + (size_t)b * T_IN * M_LEN + m;
    bool c0 = (m - 1 >= 0);
    bool c2 = (m + 1 < M_LEN);

    float win[4][3];   // rows t-2..t+1, cols m-1..m+1
#pragma unroll
    for (int i = 0; i < 4; ++i)
#pragma unroll
        for (int j = 0; j < 3; ++j) win[i][j] = 0.0f;
    // preload rows 0 and 1 (for t=0: rows -2,-1 are zero)
#pragma unroll
    for (int i = 2; i < 4; ++i) {
        int ti = i - 2;
        win[i][0] = c0 ? xb[ti * M_LEN - 1] : 0.0f;
        win[i][1] = xb[ti * M_LEN];
        win[i][2] = c2 ? xb[ti * M_LEN + 1] : 0.0f;
    }

    float v = 0.0f;
    for (int t = 0; t < T_LEN; ++t) {
        float acc = 0.0f;
#pragma unroll
        for (int kh = 0; kh < 4; ++kh)
#pragma unroll
            for (int kw = 0; kw < 3; ++kw)
                acc = fmaf(wr[kh * 3 + kw], win[kh][kw], acc);

        v = v + lif_tau_div(acc - v);
        bool sp = (v >= 1.0f);
        if (sp) v = 0.0f;
        unsigned bal = __ballot_sync(0xffffffffu, sp);
        if (lane == 0)
            g_mask1[((b * T_LEN + t) * M_LEN + m) * 2 + half] = bal;

        // shift window, load row t+2
#pragma unroll
        for (int i = 0; i < 3; ++i)
#pragma unroll
            for (int j = 0; j < 3; ++j) win[i][j] = win[i + 1][j];
        int ti = t + 2;
        bool rv = (ti < T_IN);
        win[3][0] = (rv && c0) ? xb[ti * M_LEN - 1] : 0.0f;
        win[3][1] = rv ? xb[ti * M_LEN] : 0.0f;
        win[3][2] = (rv && c2) ? xb[ti * M_LEN + 1] : 0.0f;
    }
}

// ---------------- LIF scan: warp per (b,m,half), lane = one chain ----------------
// MODE 0: emit bitmasks. MODE 1: emit spike counts.
template<int MODE>
__global__ void __launch_bounds__(1024) k_lif_scan(const float* __restrict__ acts,
                                                   unsigned* __restrict__ mask_out) {
    int w    = (blockIdx.x * 1024 + threadIdx.x) >> 5;
    int lane = threadIdx.x & 31;
    int b    = w / 80;
    int r    = w % 80;
    int m    = r >> 1;
    int half = r & 1;
    const float* p = acts + ((size_t)b * T_LEN * M_LEN + m) * 64 + half * 32 + lane;

    float v = 0.0f, cnt = 0.0f;
    float nxt = p[0];
    for (int t = 0; t < T_LEN; ++t) {
        float a = nxt;
        if (t + 1 < T_LEN) nxt = p[(size_t)(t + 1) * M_LEN * 64];  // prefetch
        v = v + lif_tau_div(a - v);
        bool sp = (v >= 1.0f);
        if (sp) v = 0.0f;
        if (MODE == 0) {
            unsigned bal = __ballot_sync(0xffffffffu, sp);
            if (lane == 0)
                mask_out[((b * T_LEN + t) * M_LEN + m) * 2 + half] = bal;
        } else {
            cnt += sp ? 1.0f : 0.0f;
        }
    }
    if (MODE == 1)
        g_cnt[b * 2560 + m * 64 + half * 32 + lane] = cnt;
}

// ---------------- sparse conv: warp per pixel, masked weight-sum ----------------
template<int PADT, int DILT, int PADM, int DILM, int WHICH>
__global__ void __launch_bounds__(1024, 1) k_sconv(const unsigned int* __restrict__ msk32,
                                                   float* __restrict__ acts_out) {
    extern __shared__ float2 ws[];   // [tap][ci][lane] float2
    const float4* Wg = WHICH ? (const float4*)g_wt3 : (const float4*)g_wt2;
    float4* ws4 = (float4*)ws;
    for (int i = threadIdx.x; i < 12288; i += 1024) ws4[i] = Wg[i];
    __syncthreads();

    const unsigned long long* msk_in = (const unsigned long long*)msk32;
    int lane = threadIdx.x & 31;
    int wid  = (blockIdx.x * 1024 + threadIdx.x) >> 5;
    int nw   = gridDim.x * 32;

    for (int pix = wid; pix < NPIX; pix += nw) {
        int b = pix / (T_LEN * M_LEN);
        int r = pix % (T_LEN * M_LEN);
        int t = r / M_LEN;
        int m = r % M_LEN;
        float a0 = 0.f, a1 = 0.f;
#pragma unroll
        for (int kh = 0; kh < 4; ++kh) {
            int ti = t - PADT + DILT * kh;
            if ((unsigned)ti >= (unsigned)T_LEN) continue;
#pragma unroll
            for (int kw = 0; kw < 3; ++kw) {
                int mi = m - PADM + DILM * kw;
                if ((unsigned)mi >= (unsigned)M_LEN) continue;
                unsigned long long mk = msk_in[(b * T_LEN + ti) * M_LEN + mi];
                const float2* wt = ws + (kh * 3 + kw) * 2048 + lane;
                while (mk) {
                    int ci = __ffsll((long long)mk) - 1;   // ascending ci (order preserved)
                    mk &= (mk - 1);
                    float2 wv = wt[ci << 5];
                    a0 += wv.x;
                    a1 += wv.y;
                }
            }
        }
        acts_out[(size_t)pix * 64 + lane]      = a0;
        acts_out[(size_t)pix * 64 + lane + 32] = a1;
    }
}

// ---------------- FC + mean ----------------
__global__ void k_fc(const float* __restrict__ bf, float* __restrict__ out) {
    int o = blockIdx.x;
    int b = blockIdx.y;
    int tid = threadIdx.x;   // 128
    const float* wft = (const float*)g_wft;
    float p = 0.0f;
    for (int i = tid; i < 2560; i += 128)
        p = fmaf(g_cnt[b * 2560 + i], wft[o * 2560 + i], p);
#pragma unroll
    for (int off = 16; off; off >>= 1) p += __shfl_down_sync(0xffffffffu, p, off);
    __shared__ float wsum[4];
    if ((tid & 31) == 0) wsum[tid >> 5] = p;
    __syncthreads();
    if (tid == 0) {
        float tt = wsum[0] + wsum[1] + wsum[2] + wsum[3];
        out[b * 12 + o] = bf[o] + tt / 129.0f;
    }
}

#define SCONV_SMEM (12 * 64 * 64 * 4)   // 196608 bytes

extern "C" void kernel_launch(void* const* d_in, const int* in_sizes, int n_in,
                              void* d_out, int out_size) {
    const float* x  = (const float*)d_in[0];
    const float* w1 = (const float*)d_in[1];
    const float* w2 = (const float*)d_in[2];
    const float* w3 = (const float*)d_in[3];
    const float* wf = (const float*)d_in[4];
    const float* bf = (const float*)d_in[5];
    float* out = (float*)d_out;

    cudaFuncSetAttribute(k_sconv<6, 4, 3, 3, 0>,
                         cudaFuncAttributeMaxDynamicSharedMemorySize, SCONV_SMEM);
    cudaFuncSetAttribute(k_sconv<24, 16, 9, 9, 1>,
                         cudaFuncAttributeMaxDynamicSharedMemorySize, SCONV_SMEM);

    unsigned int* m1 = nullptr; cudaGetSymbolAddress((void**)&m1, g_mask1);
    unsigned int* m2 = nullptr; cudaGetSymbolAddress((void**)&m2, g_mask2);
    float* aA = nullptr; cudaGetSymbolAddress((void**)&aA, g_actA);

    k_transpose<<<504, 256>>>(w2, w3, wf);

    // layer 1: fused conv1 + LIF1 -> mask1   (2560 warps)
    k_conv1_lif<<<80, 1024>>>(x, w1);

    // layer 2: sparse conv -> LIF -> mask2
    k_sconv<6, 4, 3, 3, 0><<<148, 1024, SCONV_SMEM>>>(m1, aA);
    k_lif_scan<0><<<80, 1024>>>(aA, m2);

    // layer 3: sparse conv -> LIF -> counts
    k_sconv<24, 16, 9, 9, 1><<<148, 1024, SCONV_SMEM>>>(m2, aA);
    k_lif_scan<1><<<80, 1024>>>(aA, nullptr);

    // FC head
    k_fc<<<dim3(12, 32), 128>>>(bf, out);
}

// round 5
// speedup vs baseline: 9.1051x; 1.2549x over previous
#include <cuda_runtime.h>

#define B_LEN 32
#define T_IN  128
#define T_LEN 129
#define M_LEN 40
#define C_LEN 64
#define NPIX  (B_LEN*T_LEN*M_LEN)            // 165,120
#define NTOT  (NPIX*C_LEN)                   // 10,567,680

// acts layout: [(b*40+m)*2+half][t][32 lanes]
__device__ float  g_actA[NTOT];
// spike lists: per pixel two 32-byte sublists (half0 ci values 0..31 stored as lane id,
// half1 stored as lane id, reader adds 32). cnt: 2 bytes per pixel.
__device__ unsigned char g_cil1[NPIX * 64];
__device__ unsigned char g_cnt1[NPIX * 2];
__device__ unsigned char g_cil2[NPIX * 64];
__device__ unsigned char g_cnt2[NPIX * 2];
// Weights transposed: float idx = tap*4096 + ci*64 + lane*2 + half
__device__ float4 g_wt2[(12 * 64 * 64) / 4];
__device__ float4 g_wt3[(12 * 64 * 64) / 4];
__device__ float4 g_wft[(12 * 40 * 64) / 4]; // [o][m][c]
__device__ float  g_cnt[B_LEN * M_LEN * C_LEN]; // [b][m][c]

__device__ __forceinline__ float lif_tau_div(float num) {
    const float TAUF = 10.0f / 7.0f;
    return __fdiv_rn(num, TAUF);
}

__device__ __forceinline__ void add_f32x2(unsigned long long& acc, unsigned long long w) {
    asm("add.rn.f32x2 %0, %1, %2;" : "=l"(acc) : "l"(acc), "l"(w));
}

// ---------------- all weight transposes in one launch ----------------
__global__ void k_transpose(const float* __restrict__ w2, const float* __restrict__ w3,
                            const float* __restrict__ wf) {
    int i = blockIdx.x * 256 + threadIdx.x;
    if (i < 2 * 49152) {
        int which = i >= 49152;
        int j = i - which * 49152;
        int ci  = j & 63;
        int tap = (j >> 6) % 12;
        int co  = j / 768;
        const float* w = which ? w3 : w2;
        float* wt = which ? (float*)g_wt3 : (float*)g_wt2;
        wt[tap * 4096 + ci * 64 + (co & 31) * 2 + (co >> 5)] = w[co * 768 + ci * 12 + tap];
    } else if (i < 2 * 49152 + 30720) {
        int j = i - 2 * 49152;
        int c = j & 63;
        int m = (j >> 6) % 40;
        int o = j / 2560;
        ((float*)g_wft)[j] = wf[o * 2560 + c * 40 + m];
    }
}

// ---------------- spike emit: ballot -> compact byte list ----------------
__device__ __forceinline__ void emit_spikes(bool sp, int lane, unsigned lml,
                                            int pix, int half,
                                            unsigned char* __restrict__ cil,
                                            unsigned char* __restrict__ cnt) {
    unsigned bal = __ballot_sync(0xffffffffu, sp);
    if (sp)
        cil[(size_t)pix * 64 + half * 32 + __popc(bal & lml)] = (unsigned char)lane;
    if (lane == 0)
        cnt[pix * 2 + half] = (unsigned char)__popc(bal);
}

// ---------------- conv1 + LIF1 fused: warp per (b,m,half) chain ----------------
__global__ void __launch_bounds__(256) k_conv1_lif(const float* __restrict__ x,
                                                   const float* __restrict__ w1) {
    int w    = (blockIdx.x * 256 + threadIdx.x) >> 5;
    int lane = threadIdx.x & 31;
    unsigned lml = (1u << lane) - 1u;
    int b    = w / 80;
    int r    = w % 80;
    int m    = r >> 1;
    int half = r & 1;
    int co   = half * 32 + lane;

    float wr[12];
#pragma unroll
    for (int k = 0; k < 12; ++k) wr[k] = w1[co * 12 + k];

    const float* xb = x + (size_t)b * T_IN * M_LEN + m;
    bool c0 = (m - 1 >= 0);
    bool c2 = (m + 1 < M_LEN);

    float win[4][3];
#pragma unroll
    for (int i = 0; i < 4; ++i)
#pragma unroll
        for (int j = 0; j < 3; ++j) win[i][j] = 0.0f;
#pragma unroll
    for (int i = 2; i < 4; ++i) {
        int ti = i - 2;
        win[i][0] = c0 ? xb[ti * M_LEN - 1] : 0.0f;
        win[i][1] = xb[ti * M_LEN];
        win[i][2] = c2 ? xb[ti * M_LEN + 1] : 0.0f;
    }

    float v = 0.0f;
    for (int t = 0; t < T_LEN; ++t) {
        float acc = 0.0f;
#pragma unroll
        for (int kh = 0; kh < 4; ++kh)
#pragma unroll
            for (int kw = 0; kw < 3; ++kw)
                acc = fmaf(wr[kh * 3 + kw], win[kh][kw], acc);

        v = v + lif_tau_div(acc - v);
        bool sp = (v >= 1.0f);
        if (sp) v = 0.0f;
        emit_spikes(sp, lane, lml, (b * T_LEN + t) * M_LEN + m, half, g_cil1, g_cnt1);

#pragma unroll
        for (int i = 0; i < 3; ++i)
#pragma unroll
            for (int j = 0; j < 3; ++j) win[i][j] = win[i + 1][j];
        int ti = t + 2;
        bool rv = (ti < T_IN);
        win[3][0] = (rv && c0) ? xb[ti * M_LEN - 1] : 0.0f;
        win[3][1] = rv ? xb[ti * M_LEN] : 0.0f;
        win[3][2] = (rv && c2) ? xb[ti * M_LEN + 1] : 0.0f;
    }
}

// ---------------- LIF scan: warp per (b,m,half); 8-deep prefetch ----------------
// MODE 0: emit spike lists. MODE 1: emit float spike counts into g_cnt.
template<int MODE>
__global__ void __launch_bounds__(256) k_lif_scan(const float* __restrict__ acts,
                                                  unsigned char* __restrict__ cil,
                                                  unsigned char* __restrict__ cntb) {
    int w    = (blockIdx.x * 256 + threadIdx.x) >> 5;
    int lane = threadIdx.x & 31;
    unsigned lml = (1u << lane) - 1u;
    int b    = w / 80;
    int r    = w % 80;
    int m    = r >> 1;
    int half = r & 1;
    const float* p = acts + ((size_t)((b * M_LEN + m) * 2 + half) * T_LEN) * 32 + lane;

    float v = 0.0f, scnt = 0.0f;
    float buf[8];
#pragma unroll
    for (int i = 0; i < 8; ++i) buf[i] = p[i * 32];

    for (int t8 = 0; t8 < 128; t8 += 8) {
#pragma unroll
        for (int k = 0; k < 8; ++k) {
            int t = t8 + k;
            float a = buf[k];
            int tn = t + 8;
            if (tn < T_LEN) buf[k] = p[tn * 32];
            v = v + lif_tau_div(a - v);
            bool sp = (v >= 1.0f);
            if (sp) v = 0.0f;
            if (MODE == 0)
                emit_spikes(sp, lane, lml, (b * T_LEN + t) * M_LEN + m, half, cil, cntb);
            else
                scnt += sp ? 1.0f : 0.0f;
        }
    }
    {   // t = 128 (buf[0] holds it)
        float a = buf[0];
        v = v + lif_tau_div(a - v);
        bool sp = (v >= 1.0f);
        if (sp) v = 0.0f;
        if (MODE == 0)
            emit_spikes(sp, lane, lml, (b * T_LEN + 128) * M_LEN + m, half, cil, cntb);
        else
            scnt += sp ? 1.0f : 0.0f;
    }
    if (MODE == 1)
        g_cnt[b * 2560 + m * 64 + half * 32 + lane] = scnt;
}

// ---------------- sparse conv: warp per pixel, list-driven weight-sum ----------------
template<int PADT, int DILT, int PADM, int DILM, int WHICH>
__global__ void __launch_bounds__(1024, 1) k_sconv(const unsigned char* __restrict__ cil,
                                                   const unsigned char* __restrict__ cntb,
                                                   float* __restrict__ acts_out) {
    extern __shared__ float2 ws[];   // [tap][ci][lane] float2
    const float4* Wg = WHICH ? (const float4*)g_wt3 : (const float4*)g_wt2;
    float4* ws4 = (float4*)ws;
    for (int i = threadIdx.x; i < 12288; i += 1024) ws4[i] = Wg[i];
    __syncthreads();

    int lane = threadIdx.x & 31;
    int wid  = (blockIdx.x * 1024 + threadIdx.x) >> 5;
    int nw   = gridDim.x * 32;
    const char* wlane = ((const char*)ws) + lane * 8;

    for (int pix = wid; pix < NPIX; pix += nw) {
        int b = pix / (T_LEN * M_LEN);
        int r = pix % (T_LEN * M_LEN);
        int t = r / M_LEN;
        int m = r % M_LEN;
        unsigned long long acc = 0ull;   // packed {a0, a1} = 0.0f,0.0f
#pragma unroll
        for (int kh = 0; kh < 4; ++kh) {
            int ti = t - PADT + DILT * kh;
            if ((unsigned)ti >= (unsigned)T_LEN) continue;
#pragma unroll
            for (int kw = 0; kw < 3; ++kw) {
                int mi = m - PADM + DILM * kw;
                if ((unsigned)mi >= (unsigned)M_LEN) continue;
                int inpix = (b * T_LEN + ti) * M_LEN + mi;
                unsigned cc = *(const unsigned short*)(cntb + inpix * 2);
                int n0 = cc & 255;
                int n1 = cc >> 8;
                const unsigned* lp = (const unsigned*)(cil + (size_t)inpix * 64);
                const char* wtap = wlane + (kh * 3 + kw) * 16384;
                for (int j = 0; j < n0; j += 4) {
                    unsigned q = lp[j >> 2];
#pragma unroll
                    for (int k = 0; k < 4; ++k) {
                        if (j + k < n0) {
                            int ci = __byte_perm(q, 0, 0x4440 + k);
                            add_f32x2(acc, *(const unsigned long long*)(wtap + ci * 256));
                        }
                    }
                }
                const char* wtap1 = wtap + 32 * 256;
                for (int j = 0; j < n1; j += 4) {
                    unsigned q = lp[8 + (j >> 2)];
#pragma unroll
                    for (int k = 0; k < 4; ++k) {
                        if (j + k < n1) {
                            int ci = __byte_perm(q, 0, 0x4440 + k);
                            add_f32x2(acc, *(const unsigned long long*)(wtap1 + ci * 256));
                        }
                    }
                }
            }
        }
        union { unsigned long long u; float2 f; } cv;
        cv.u = acc;
        size_t row = (size_t)((b * M_LEN + m) * 2) * T_LEN + t;
        acts_out[row * 32 + lane]                   = cv.f.x;
        acts_out[(row + T_LEN) * 32 + lane]         = cv.f.y;
    }
}

// ---------------- FC + mean ----------------
__global__ void k_fc(const float* __restrict__ bf, float* __restrict__ out) {
    int o = blockIdx.x;
    int b = blockIdx.y;
    int tid = threadIdx.x;   // 128
    const float* wft = (const float*)g_wft;
    float p = 0.0f;
    for (int i = tid; i < 2560; i += 128)
        p = fmaf(g_cnt[b * 2560 + i], wft[o * 2560 + i], p);
#pragma unroll
    for (int off = 16; off; off >>= 1) p += __shfl_down_sync(0xffffffffu, p, off);
    __shared__ float wsum[4];
    if ((tid & 31) == 0) wsum[tid >> 5] = p;
    __syncthreads();
    if (tid == 0) {
        float tt = wsum[0] + wsum[1] + wsum[2] + wsum[3];
        out[b * 12 + o] = bf[o] + tt / 129.0f;
    }
}

#define SCONV_SMEM (12 * 64 * 64 * 4)   // 196608 bytes

extern "C" void kernel_launch(void* const* d_in, const int* in_sizes, int n_in,
                              void* d_out, int out_size) {
    const float* x  = (const float*)d_in[0];
    const float* w1 = (const float*)d_in[1];
    const float* w2 = (const float*)d_in[2];
    const float* w3 = (const float*)d_in[3];
    const float* wf = (const float*)d_in[4];
    const float* bf = (const float*)d_in[5];
    float* out = (float*)d_out;

    cudaFuncSetAttribute(k_sconv<6, 4, 3, 3, 0>,
                         cudaFuncAttributeMaxDynamicSharedMemorySize, SCONV_SMEM);
    cudaFuncSetAttribute(k_sconv<24, 16, 9, 9, 1>,
                         cudaFuncAttributeMaxDynamicSharedMemorySize, SCONV_SMEM);

    unsigned char* c1 = nullptr; cudaGetSymbolAddress((void**)&c1, g_cil1);
    unsigned char* n1 = nullptr; cudaGetSymbolAddress((void**)&n1, g_cnt1);
    unsigned char* c2 = nullptr; cudaGetSymbolAddress((void**)&c2, g_cil2);
    unsigned char* n2 = nullptr; cudaGetSymbolAddress((void**)&n2, g_cnt2);
    float* aA = nullptr; cudaGetSymbolAddress((void**)&aA, g_actA);

    k_transpose<<<504, 256>>>(w2, w3, wf);

    // layer 1: fused conv1 + LIF1 -> list1
    k_conv1_lif<<<320, 256>>>(x, w1);

    // layer 2: sparse conv -> acts -> LIF -> list2
    k_sconv<6, 4, 3, 3, 0><<<148, 1024, SCONV_SMEM>>>(c1, n1, aA);
    k_lif_scan<0><<<320, 256>>>(aA, c2, n2);

    // layer 3: sparse conv -> acts -> LIF -> counts
    k_sconv<24, 16, 9, 9, 1><<<148, 1024, SCONV_SMEM>>>(c2, n2, aA);
    k_lif_scan<1><<<320, 256>>>(aA, nullptr, nullptr);

    // FC head
    k_fc<<<dim3(12, 32), 128>>>(bf, out);
}